// round 15
// baseline (speedup 1.0000x reference)
#include <cuda_runtime.h>
#include <cuda_fp16.h>

#define BIG 1e9f
#define FULLMASK 0xFFFFFFFFu

// 32-thread blocks, TWO images per warp: lanes 0-15 -> image 2b, 16-31 -> 2b+1.
// Each lane owns 4 rows (4sl..4sl+3): cells A,B,C,D on wavefront t=i+j=1..126.
// Potential transform z = d + img/2: z[i][j] = img[i][j] + min(zL, zU, zD).
// Staging pipelined with compute: image staged in 16-row batches; wavefront
// step t only needs rows <= t, so step segments run while the next batch's
// LDGs are in flight. smem pre-zeroed so any out-of-window read of not-yet-
// staged data is finite (absorbed by the ~1e9 sentinel min logic).
// fp16 image in smem; per image chunk: [sA 32x68][sB 32x68][pad 2] halves =
// 2177 words (odd stride) -> image0 lanes even banks, image1 odd banks:
// all LDS/STS conflict-free. NOTE: odd word stride makes chunk 1 only 4-byte
// aligned -> all smem stores must be <= 4 bytes (half2), never vectorized.
// Streams (scalar base 132*sl):
//   xA(t)=sA[132sl+t] xB(t)=sB[132sl+t-1] xC(t)=sA[132sl+t+66] xD(t)=sB[132sl+t+65]
__global__ void __launch_bounds__(32) dp_wavefront_kernel(
    const float* __restrict__ img, float* __restrict__ out, int B)
{
    __shared__ __half smem[2][4354];            // 2 image chunks, odd word stride

    const int lane = threadIdx.x;               // 0..31
    const int sl = lane & 15;
    int img_idx = blockIdx.x * 2 + (lane >> 4);
    const bool valid = (img_idx < B);
    if (!valid) img_idx = B - 1;                // keep lanes resident for shfl

    __half* sA = smem[lane >> 4];
    __half* sB = sA + 2176;

    // ---- zero entire block smem: out-of-window reads must be finite ----
    {
        uint4* z4 = reinterpret_cast<uint4*>(&smem[0][0]);   // 17416 B total, base 16B-aligned
        #pragma unroll
        for (int i = 0; i < 34; i++)                          // 34*32*16 = 17408
            z4[i * 32 + lane] = make_uint4(0, 0, 0, 0);
        if (lane == 0) {                                      // last 8 bytes, 8B-aligned
            unsigned* tail = reinterpret_cast<unsigned*>(reinterpret_cast<char*>(z4) + 17408);
            tail[0] = 0; tail[1] = 0;
        }
        __syncwarp();
    }

    const float4* g4 = reinterpret_cast<const float4*>(img + (size_t)img_idx * 4096);
    float4 v[16];

#define LOAD_BATCH(b) do { \
    _Pragma("unroll") \
    for (int k_ = 0; k_ < 16; k_++) v[k_] = g4[((b) * 16 + k_) * 16 + sl]; \
} while (0)

// two 4-byte half2 stores (chunk 1 base is only 4-byte aligned)
#define STORE_BATCH(b) do { \
    _Pragma("unroll") \
    for (int k_ = 0; k_ < 16; k_++) { \
        int r_ = (b) * 16 + k_; \
        __half2* dst_ = reinterpret_cast<__half2*>( \
            ((r_ & 1) ? sB : sA) + 68 * (r_ >> 1) + 4 * sl); \
        dst_[0] = __floats2half2_rn(v[k_].x, v[k_].y); \
        dst_[1] = __floats2half2_rn(v[k_].z, v[k_].w); \
    } \
} while (0)

    // stream word pointers: wA[k]=(xA(2k),xA(2k+1)) wC likewise;
    // wB[k]=(xB(2k+1),xB(2k+2)) wD likewise (carry xB/xD(2k) across pairs)
    const __half2* wA = reinterpret_cast<const __half2*>(sA) + 66 * sl;
    const __half2* wC = wA + 33;
    const __half2* wB = reinterpret_cast<const __half2*>(sB) + 66 * sl;
    const __half2* wD = wB + 33;

    float zA1, zA2 = BIG, zB1 = BIG, zB2 = BIG, zC1 = BIG, zC2 = BIG, zD1 = BIG, zL2 = BIG;
    float bc, dc;

#define PAIR_STEP(k) do { \
    float2 av_ = __half22float2(wA[k]); \
    float2 cv_ = __half22float2(wC[k]); \
    float2 bv_ = __half22float2(wB[k]); \
    float2 dv_ = __half22float2(wD[k]); \
    float xB0_ = bc; bc = bv_.y; \
    float xD0_ = dc; dc = dv_.y; \
    float zLa_ = __shfl_up_sync(FULLMASK, zD1, 1, 16); \
    if (sl == 0) zLa_ = BIG; \
    float zAn_ = av_.x + fminf(fminf(zA1, zLa_), zL2); \
    float zBn_ = xB0_ + fminf(zB1, fminf(zA1, zA2)); \
    float zCn_ = cv_.x + fminf(zC1, fminf(zB1, zB2)); \
    float zDn_ = xD0_ + fminf(zD1, fminf(zC1, zC2)); \
    zA2 = zA1; zA1 = zAn_; zB2 = zB1; zB1 = zBn_; \
    zC2 = zC1; zC1 = zCn_; zD1 = zDn_; zL2 = zLa_; \
    float zLb_ = __shfl_up_sync(FULLMASK, zD1, 1, 16); \
    if (sl == 0) zLb_ = BIG; \
    zAn_ = av_.y + fminf(fminf(zA1, zLb_), zL2); \
    zBn_ = bv_.x + fminf(zB1, fminf(zA1, zA2)); \
    zCn_ = cv_.y + fminf(zC1, fminf(zB1, zB2)); \
    zDn_ = dv_.x + fminf(zD1, fminf(zC1, zC2)); \
    zA2 = zA1; zA1 = zAn_; zB2 = zB1; zB1 = zBn_; \
    zC2 = zC1; zC1 = zCn_; zD1 = zDn_; zL2 = zLb_; \
} while (0)

    // ---- batch 0 (rows 0-15): load + store + sync ----
    LOAD_BATCH(0);
    STORE_BATCH(0);
    __syncwarp();
    LOAD_BATCH(1);                    // in flight during segment 0

    // ---- segment 0: prologue t=1 + pairs k=1..6 (t<=13, rows<16) ----
    {
        float2 a0 = __half22float2(wA[0]);      // xA(0), xA(1)
        float2 b0 = __half22float2(wB[0]);      // xB(1), xB(2)
        float2 c0 = __half22float2(wC[0]);      // xC(0), xC(1)
        float2 d0 = __half22float2(wD[0]);      // xD(1), xD(2)
        zA1 = (sl == 0) ? 0.5f * a0.x : BIG;    // z(0,0)

        float zLa = __shfl_up_sync(FULLMASK, zD1, 1, 16);
        if (sl == 0) zLa = BIG;
        float zAn = a0.y + fminf(fminf(zA1, zLa), zL2);
        float zBn = b0.x + fminf(zB1, fminf(zA1, zA2));
        float zCn = c0.y + fminf(zC1, fminf(zB1, zB2));
        float zDn = d0.x + fminf(zD1, fminf(zC1, zC2));
        zA2 = zA1; zA1 = zAn; zB2 = zB1; zB1 = zBn;
        zC2 = zC1; zC1 = zCn; zD1 = zDn; zL2 = zLa;
        bc = b0.y; dc = d0.y;                   // carried xB(2), xD(2)
    }
    #pragma unroll 2
    for (int k = 1; k < 7; k++) PAIR_STEP(k);

    STORE_BATCH(1);
    __syncwarp();
    LOAD_BATCH(2);

    // ---- segment 1: pairs k=7..14 (t<=29, rows<32) ----
    #pragma unroll 2
    for (int k = 7; k < 15; k++) PAIR_STEP(k);

    STORE_BATCH(2);
    __syncwarp();
    LOAD_BATCH(3);

    // ---- segment 2: pairs k=15..22 (t<=45, rows<48) ----
    #pragma unroll 2
    for (int k = 15; k < 23; k++) PAIR_STEP(k);

    STORE_BATCH(3);
    __syncwarp();

    // ---- segment 3: pairs k=23..62 (t<=125) ----
    #pragma unroll 2
    for (int k = 23; k < 63; k++) PAIR_STEP(k);

    // ---- t = 126: only the D cell feeds the answer; dc = xD(126) = img[63][63]
    float zDfin = dc + fminf(zD1, fminf(zC1, zC2));

    // d[63][63] = z - 0.5*img[63][63]; (63,63) is lane sl=15's D cell
    if (sl == 15 && valid) out[img_idx] = zDfin - 0.5f * dc;

#undef LOAD_BATCH
#undef STORE_BATCH
#undef PAIR_STEP
}

extern "C" void kernel_launch(void* const* d_in, const int* in_sizes, int n_in,
                              void* d_out, int out_size) {
    const float* img = (const float*)d_in[0];
    float* out = (float*)d_out;
    int B = in_sizes[0] / (64 * 64);
    int blocks = (B + 1) / 2;            // 2 images per 32-thread block (1 warp)
    dp_wavefront_kernel<<<blocks, 32>>>(img, out, B);
}